// round 2
// baseline (speedup 1.0000x reference)
#include <cuda_runtime.h>
#include <math.h>

#define T_STEPS 512
#define BATCH   64
#define DDIM    512
#define HDIM    512
#define G3      1536   // 3*HDIM

// ---------------- static device scratch (no allocations allowed) ----------------
__device__ float g_gi[(size_t)T_STEPS * BATCH * G3];   // 192 MB: precomputed x@Wi + bi
__device__ float g_h[BATCH * HDIM];                    // recurrent hidden state buffer
__device__ int   g_bar[8];                             // per-batch-group barrier counters

// ---------------- barrier reset (graph-replay determinism) ----------------
__global__ void gru_reset_kernel() {
    if (threadIdx.x < 8) g_bar[threadIdx.x] = 0;
}

// ---------------- Phase 1: GI = X @ Wi + bi   (M=32768, K=512, N=1536) ----------------
__global__ __launch_bounds__(256) void gi_gemm_kernel(
    const float* __restrict__ X, const float* __restrict__ Wi, const float* __restrict__ bi)
{
    __shared__ float As[8][128];   // As[k][m]
    __shared__ float Bs[8][128];   // Bs[k][n]
    const int tid = threadIdx.x;
    const int bx  = blockIdx.x;    // N tile (12)
    const int by  = blockIdx.y;    // M tile (256)
    const int tx  = tid & 15;
    const int ty  = tid >> 4;

    float acc[8][8];
    #pragma unroll
    for (int i = 0; i < 8; ++i)
        #pragma unroll
        for (int j = 0; j < 8; ++j) acc[i][j] = 0.f;

    const int arow_l = tid >> 1;
    const int acol_l = (tid & 1) * 4;
    const int brow_l = tid >> 5;
    const int bcol_l = (tid & 31) * 4;
    const float* Aptr = X  + (size_t)(by * 128 + arow_l) * DDIM + acol_l;
    const float* Bptr = Wi + (size_t)brow_l * G3 + bx * 128 + bcol_l;

    for (int kk = 0; kk < DDIM; kk += 8) {
        float4 av = *(const float4*)(Aptr + kk);
        float4 bv = *(const float4*)(Bptr + (size_t)kk * G3);
        As[acol_l + 0][arow_l] = av.x;
        As[acol_l + 1][arow_l] = av.y;
        As[acol_l + 2][arow_l] = av.z;
        As[acol_l + 3][arow_l] = av.w;
        *(float4*)&Bs[brow_l][bcol_l] = bv;
        __syncthreads();
        #pragma unroll
        for (int k = 0; k < 8; ++k) {
            float4 a0 = *(const float4*)&As[k][ty * 8];
            float4 a1 = *(const float4*)&As[k][ty * 8 + 4];
            float4 b0 = *(const float4*)&Bs[k][tx * 8];
            float4 b1 = *(const float4*)&Bs[k][tx * 8 + 4];
            float a[8] = {a0.x, a0.y, a0.z, a0.w, a1.x, a1.y, a1.z, a1.w};
            float b[8] = {b0.x, b0.y, b0.z, b0.w, b1.x, b1.y, b1.z, b1.w};
            #pragma unroll
            for (int i = 0; i < 8; ++i)
                #pragma unroll
                for (int j = 0; j < 8; ++j)
                    acc[i][j] = fmaf(a[i], b[j], acc[i][j]);
        }
        __syncthreads();
    }

    const int row0 = by * 128 + ty * 8;
    const int col0 = bx * 128 + tx * 8;
    float bvv[8];
    #pragma unroll
    for (int j = 0; j < 8; ++j) bvv[j] = bi[col0 + j];
    #pragma unroll
    for (int i = 0; i < 8; ++i) {
        float* orow = g_gi + (size_t)(row0 + i) * G3 + col0;
        float4 o0 = make_float4(acc[i][0] + bvv[0], acc[i][1] + bvv[1],
                                acc[i][2] + bvv[2], acc[i][3] + bvv[3]);
        float4 o1 = make_float4(acc[i][4] + bvv[4], acc[i][5] + bvv[5],
                                acc[i][6] + bvv[6], acc[i][7] + bvv[7]);
        *(float4*)(orow)     = o0;
        *(float4*)(orow + 4) = o1;
    }
}

// ---------------- Phase 2: persistent recurrence ----------------
// Grid: 128 CTAs = 8 batch-groups (8 batch rows each) x 16 column-CTAs (32 h-cols each).
// Each CTA keeps Wh slice [512][96] resident in SMEM for all 512 steps.

__device__ __forceinline__ int ld_acquire_gpu(const int* p) {
    int v;
    asm volatile("ld.acquire.gpu.s32 %0, [%1];" : "=r"(v) : "l"(p) : "memory");
    return v;
}

#define H_PAD 516                                    // padded row: banks {0,8,16,24} per b-group
#define REC_SMEM_FLOATS (512 * 96 + 8 * H_PAD + 4 * 32 * 24)
#define REC_SMEM_BYTES  (REC_SMEM_FLOATS * 4)        // 225,408 B

__global__ __launch_bounds__(128) void gru_rec_kernel(
    const float* __restrict__ h0, const float* __restrict__ Wh,
    const float* __restrict__ bhn, float* __restrict__ out)
{
    extern __shared__ float sm[];
    float* Whs   = sm;                   // [512][96]  (rows 384B -> 128B aligned)
    float* h_s   = sm + 512 * 96;        // [8][516]
    float* parts = h_s + 8 * H_PAD;      // [4 ksplit][32 og][24]

    const int tid  = threadIdx.x;
    const int bg   = blockIdx.x >> 4;    // batch group 0..7
    const int ic   = blockIdx.x & 15;    // col group 0..15
    const int lane = tid & 31;
    const int ks   = tid >> 5;           // warp index = k-split 0..3
    const int b0   = (lane >> 3) * 2;    // thread tile: 2 batch rows
    const int c0   = (lane & 7) * 4;     // thread tile: 4 cols per gate

    // --- one-time: load Wh slice into SMEM: Whs[k][g*32+cc] = Wh[k][g*512 + ic*32 + cc]
    for (int q = tid; q < 512 * 24; q += 128) {
        int k  = q / 24;
        int c4 = (q - k * 24) * 4;
        int g  = c4 >> 5;
        int cc = c4 & 31;
        float4 v = *(const float4*)&Wh[(size_t)k * G3 + g * 512 + ic * 32 + cc];
        *(float4*)&Whs[k * 96 + c4] = v;
    }

    // Output assignment: thread handles h_new (obA, occ0) and (obB, occ0)
    const int occ0 = tid & 31;           // column within the 32-col block
    const int obA  = tid >> 5;           // batch row 0..3
    const int obB  = obA + 4;            // batch row 4..7
    const int ci   = occ0 & 3;
    const int cgrp = occ0 >> 2;
    const int ogA  = (obA >> 1) * 8 + cgrp;
    const int ogB  = (obB >> 1) * 8 + cgrp;
    const int bb   = obA & 1;            // same for obB (+4 preserves bit 0)
    const int hcol = ic * 32 + occ0;     // global hidden column
    const float bh = bhn[hcol];

    __syncthreads();

    for (int t = 0; t < T_STEPS; ++t) {
        // --- load this batch group's h into SMEM (padded rows) ---
        const float* hsrc = (t == 0) ? (h0 + (size_t)bg * 8 * HDIM)
                                     : (g_h + (size_t)bg * 8 * HDIM);
        #pragma unroll 2
        for (int q = tid; q < 1024; q += 128) {
            int b  = q >> 7;
            int kq = (q & 127) * 4;
            float4 v = *(const float4*)&hsrc[b * HDIM + kq];
            *(float4*)&h_s[b * H_PAD + kq] = v;
        }
        // --- prefetch gi values (DRAM latency hidden behind the GEMM) ---
        const float* giA = g_gi + ((size_t)t * BATCH + bg * 8 + obA) * G3 + hcol;
        const float* giB = g_gi + ((size_t)t * BATCH + bg * 8 + obB) * G3 + hcol;
        float grA = giA[0], gzA = giA[512], gnA = giA[1024];
        float grB = giB[0], gzB = giB[512], gnB = giB[1024];
        __syncthreads();

        // --- register-tiled GEMM: gh[2 b][4 c x 3 gates], warp = 128-wide k-split ---
        float acc[24];
        #pragma unroll
        for (int i = 0; i < 24; ++i) acc[i] = 0.f;
        const float* hA = &h_s[b0 * H_PAD + ks * 128];
        const float* hB = &h_s[(b0 + 1) * H_PAD + ks * 128];
        const float* wp = &Whs[(ks * 128) * 96 + c0];
        #pragma unroll 8
        for (int i = 0; i < 128; ++i) {
            float a0 = hA[i];
            float a1 = hB[i];
            float4 wr = *(const float4*)(wp);
            float4 wz = *(const float4*)(wp + 32);
            float4 wn = *(const float4*)(wp + 64);
            acc[0]  = fmaf(a0, wr.x, acc[0]);  acc[1]  = fmaf(a0, wr.y, acc[1]);
            acc[2]  = fmaf(a0, wr.z, acc[2]);  acc[3]  = fmaf(a0, wr.w, acc[3]);
            acc[4]  = fmaf(a0, wz.x, acc[4]);  acc[5]  = fmaf(a0, wz.y, acc[5]);
            acc[6]  = fmaf(a0, wz.z, acc[6]);  acc[7]  = fmaf(a0, wz.w, acc[7]);
            acc[8]  = fmaf(a0, wn.x, acc[8]);  acc[9]  = fmaf(a0, wn.y, acc[9]);
            acc[10] = fmaf(a0, wn.z, acc[10]); acc[11] = fmaf(a0, wn.w, acc[11]);
            acc[12] = fmaf(a1, wr.x, acc[12]); acc[13] = fmaf(a1, wr.y, acc[13]);
            acc[14] = fmaf(a1, wr.z, acc[14]); acc[15] = fmaf(a1, wr.w, acc[15]);
            acc[16] = fmaf(a1, wz.x, acc[16]); acc[17] = fmaf(a1, wz.y, acc[17]);
            acc[18] = fmaf(a1, wz.z, acc[18]); acc[19] = fmaf(a1, wz.w, acc[19]);
            acc[20] = fmaf(a1, wn.x, acc[20]); acc[21] = fmaf(a1, wn.y, acc[21]);
            acc[22] = fmaf(a1, wn.z, acc[22]); acc[23] = fmaf(a1, wn.w, acc[23]);
            wp += 96;
        }
        // --- stage k-split partials ---
        float* pp = &parts[(ks * 32 + lane) * 24];
        *(float4*)(pp + 0)  = make_float4(acc[0],  acc[1],  acc[2],  acc[3]);
        *(float4*)(pp + 4)  = make_float4(acc[4],  acc[5],  acc[6],  acc[7]);
        *(float4*)(pp + 8)  = make_float4(acc[8],  acc[9],  acc[10], acc[11]);
        *(float4*)(pp + 12) = make_float4(acc[12], acc[13], acc[14], acc[15]);
        *(float4*)(pp + 16) = make_float4(acc[16], acc[17], acc[18], acc[19]);
        *(float4*)(pp + 20) = make_float4(acc[20], acc[21], acc[22], acc[23]);
        __syncthreads();

        // --- reduce k-splits + gates + write (2 h-outputs per thread) ---
        {
            const float* pA = &parts[ogA * 24 + bb * 12 + ci];
            float sr = 0.f, sz = 0.f, sn = 0.f;
            #pragma unroll
            for (int k2 = 0; k2 < 4; ++k2) {
                const float* q = pA + k2 * (32 * 24);
                sr += q[0]; sz += q[4]; sn += q[8];
            }
            float rr   = 1.f / (1.f + __expf(-(grA + sr)));
            float zz   = 1.f / (1.f + __expf(-(gzA + sz)));
            float nn   = tanhf(gnA + rr * (sn + bh));
            float hold = h_s[obA * H_PAD + hcol];
            float hnew = (1.f - zz) * nn + zz * hold;
            int brow = bg * 8 + obA;
            g_h[brow * HDIM + hcol] = hnew;
            out[((size_t)t * BATCH + brow) * HDIM + hcol] = hnew;
        }
        {
            const float* pB = &parts[ogB * 24 + bb * 12 + ci];
            float sr = 0.f, sz = 0.f, sn = 0.f;
            #pragma unroll
            for (int k2 = 0; k2 < 4; ++k2) {
                const float* q = pB + k2 * (32 * 24);
                sr += q[0]; sz += q[4]; sn += q[8];
            }
            float rr   = 1.f / (1.f + __expf(-(grB + sr)));
            float zz   = 1.f / (1.f + __expf(-(gzB + sz)));
            float nn   = tanhf(gnB + rr * (sn + bh));
            float hold = h_s[obB * H_PAD + hcol];
            float hnew = (1.f - zz) * nn + zz * hold;
            int brow = bg * 8 + obB;
            g_h[brow * HDIM + hcol] = hnew;
            out[((size_t)t * BATCH + brow) * HDIM + hcol] = hnew;
        }

        // --- 16-CTA batch-group barrier (monotonic counter, release/acquire) ---
        __threadfence();
        __syncthreads();
        if (tid == 0) {
            atomicAdd(&g_bar[bg], 1);
            const int target = (t + 1) * 16;
            while (ld_acquire_gpu(&g_bar[bg]) < target) { }
        }
        __syncthreads();
    }
}

// ---------------- launch ----------------
extern "C" void kernel_launch(void* const* d_in, const int* in_sizes, int n_in,
                              void* d_out, int out_size)
{
    const float* x   = (const float*)d_in[0];   // [T,B,D]
    const float* h0  = (const float*)d_in[1];   // [B,H]
    const float* Wi  = (const float*)d_in[2];   // [D,3H]
    const float* Wh  = (const float*)d_in[3];   // [H,3H]
    const float* bi  = (const float*)d_in[4];   // [3H]
    const float* bhn = (const float*)d_in[5];   // [H]
    float* out = (float*)d_out;                 // [T,B,H]
    (void)in_sizes; (void)n_in; (void)out_size;

    cudaFuncSetAttribute(gru_rec_kernel,
                         cudaFuncAttributeMaxDynamicSharedMemorySize, REC_SMEM_BYTES);

    gru_reset_kernel<<<1, 32>>>();

    dim3 g1(G3 / 128, (T_STEPS * BATCH) / 128);   // (12, 256)
    gi_gemm_kernel<<<g1, 256>>>(x, Wi, bi);

    gru_rec_kernel<<<128, 128, REC_SMEM_BYTES>>>(h0, Wh, bhn, out);
}